// round 1
// baseline (speedup 1.0000x reference)
#include <cuda_runtime.h>
#include <math.h>

// Problem constants
#define NB 4
#define LV 2048
#define LE 64
#define LJ 2112        // LV + LE
#define DMODEL 960
#define NH 15
#define NKVH 5
#define HD 64
#define GQ 3           // NH / NKVH
#define QN (NH*HD)     // 960
#define KVN (NKVH*HD)  // 320
#define SCALE 0.125f   // HD^-0.5

// Scratch (static device globals: allocation-free per harness rules)
__device__ float g_xn_v[NB*LV*DMODEL];
__device__ float g_xn_e[NB*LE*DMODEL];
__device__ float g_q[NB*LJ*QN];
__device__ float g_k[NB*LJ*KVN];
__device__ float g_v[NB*LJ*KVN];
__device__ float g_attn[NB*LJ*QN];

// ---------------------------------------------------------------------------
// RMSNorm: one block per row, 256 threads over D=960
// ---------------------------------------------------------------------------
__global__ void rmsnorm_kernel(const float* __restrict__ x, const float* __restrict__ w,
                               float* __restrict__ out) {
  int row = blockIdx.x;
  const float* xr = x + (size_t)row * DMODEL;
  float* orow = out + (size_t)row * DMODEL;
  int t = threadIdx.x;
  float v[4];
  float ss = 0.f;
  #pragma unroll
  for (int i = 0; i < 4; i++) {
    int idx = t + i * 256;
    v[i] = (idx < DMODEL) ? xr[idx] : 0.f;
    ss += v[i] * v[i];
  }
  #pragma unroll
  for (int o = 16; o > 0; o >>= 1) ss += __shfl_xor_sync(0xffffffffu, ss, o);
  __shared__ float wsum[8];
  if ((t & 31) == 0) wsum[t >> 5] = ss;
  __syncthreads();
  if (t < 32) {
    float s = (t < 8) ? wsum[t] : 0.f;
    #pragma unroll
    for (int o = 4; o > 0; o >>= 1) s += __shfl_xor_sync(0xffffffffu, s, o);
    if (t == 0) wsum[0] = s;
  }
  __syncthreads();
  float rms = rsqrtf(wsum[0] * (1.f / DMODEL) + 1e-6f);
  #pragma unroll
  for (int i = 0; i < 4; i++) {
    int idx = t + i * 256;
    if (idx < DMODEL) orow[idx] = v[i] * rms * w[idx];
  }
}

// ---------------------------------------------------------------------------
// Tiled SGEMM with joint-row mapping.
// Logical row m in [0,M): b = m/Lsrc, l = m%Lsrc, joint = b*LJ + l_off + l.
//   A row index  = a_joint ? joint : m      (A row stride = K)
//   C row index  = joint                    (C row stride = N)
//   resid (optional) indexed by m           (row stride = N)
// BM=BN=64, BK=16, 256 threads, 4x4 microtile. All dims divisible.
// ---------------------------------------------------------------------------
__global__ void sgemm_map(const float* __restrict__ A, const float* __restrict__ W,
                          float* __restrict__ C, const float* __restrict__ resid,
                          int M, int N, int K, int Lsrc, int l_off, int a_joint) {
  __shared__ float As[16][65];   // padded to dodge store conflicts
  __shared__ float Bs[16][64];
  int tid = threadIdx.x;
  int tx = tid & 15;
  int ty = tid >> 4;
  int m0 = blockIdx.y * 64;
  int n0 = blockIdx.x * 64;

  // A-tile load assignment: thread -> (row, 4 consecutive k)
  int a_r = tid >> 2;           // 0..63
  int a_c = (tid & 3) * 4;      // 0,4,8,12
  int am = m0 + a_r;
  int a_row = a_joint ? ((am / Lsrc) * LJ + l_off + (am % Lsrc)) : am;
  const float* Aptr = A + (size_t)a_row * K + a_c;

  // W-tile load assignment: thread -> (k-row, 4 consecutive n)
  int b_r = tid >> 4;           // 0..15
  int b_c = (tid & 15) * 4;
  const float* Wptr = W + (size_t)b_r * N + n0 + b_c;

  float c[4][4];
  #pragma unroll
  for (int i = 0; i < 4; i++)
    #pragma unroll
    for (int j = 0; j < 4; j++) c[i][j] = 0.f;

  for (int k0 = 0; k0 < K; k0 += 16) {
    float4 av = *(const float4*)(Aptr + k0);
    float4 bv = *(const float4*)(Wptr + (size_t)k0 * N);
    As[a_c + 0][a_r] = av.x;
    As[a_c + 1][a_r] = av.y;
    As[a_c + 2][a_r] = av.z;
    As[a_c + 3][a_r] = av.w;
    *(float4*)&Bs[b_r][b_c] = bv;
    __syncthreads();
    #pragma unroll
    for (int kk = 0; kk < 16; kk++) {
      float a[4], b[4];
      #pragma unroll
      for (int i = 0; i < 4; i++) a[i] = As[kk][ty * 4 + i];
      #pragma unroll
      for (int j = 0; j < 4; j++) b[j] = Bs[kk][tx * 4 + j];
      #pragma unroll
      for (int i = 0; i < 4; i++)
        #pragma unroll
        for (int j = 0; j < 4; j++) c[i][j] += a[i] * b[j];
    }
    __syncthreads();
  }

  #pragma unroll
  for (int i = 0; i < 4; i++) {
    int m = m0 + ty * 4 + i;
    int cr = (m / Lsrc) * LJ + l_off + (m % Lsrc);
    int n = n0 + tx * 4;
    float4 r;
    r.x = c[i][0]; r.y = c[i][1]; r.z = c[i][2]; r.w = c[i][3];
    if (resid) {
      float4 hh = *(const float4*)(resid + (size_t)m * N + n);
      r.x += hh.x; r.y += hh.y; r.z += hh.z; r.w += hh.w;
    }
    *(float4*)(C + (size_t)cr * N + n) = r;
  }
}

// ---------------------------------------------------------------------------
// RoPE (in-place): one 32-thread group per (joint_row, head); lane j handles
// the (j, j+32) pair. Timescale computed in fp64 to stay within ref tolerance.
// ---------------------------------------------------------------------------
__global__ void rope_kernel(float* __restrict__ buf, int nh, int npairs,
                            const int* __restrict__ pv, const int* __restrict__ pe) {
  int pair = blockIdx.x * 8 + (threadIdx.x >> 5);
  if (pair >= npairs) return;
  int j = threadIdx.x & 31;
  int h = pair % nh;
  int r = pair / nh;
  int b = r / LJ;
  int l = r - b * LJ;
  int pos = (l < LV) ? pv[b * LV + l] : pe[b * LE + (l - LV)];
  double dinv = exp((double)j * (-9.210340371976184 / 32.0));  // 10000^(-j/32)
  float rad = (float)((double)pos * dinv);
  float sn, cs;
  sincosf(rad, &sn, &cs);
  float* p = buf + (size_t)r * (nh * HD) + h * HD;
  float x1 = p[j];
  float x2 = p[j + 32];
  p[j] = x1 * cs - x2 * sn;
  p[j + 32] = x2 * cs + x1 * sn;
}

// ---------------------------------------------------------------------------
// Flash attention, fp32. One block = (128 q rows, head h, batch b).
// Each thread owns one q row (q and acc in registers as float4[16]).
// K/V tiles of 32 keys staged in smem; online softmax.
// Mask: q row l < LV attends keys [0,LV); l >= LV attends keys [0,l].
// ---------------------------------------------------------------------------
__global__ void __launch_bounds__(128) attn_kernel(const float* __restrict__ Q,
                                                   const float* __restrict__ Kb,
                                                   const float* __restrict__ Vb,
                                                   float* __restrict__ O) {
  int h = blockIdx.y, b = blockIdx.z;
  int kvh = h / GQ;
  int l = blockIdx.x * 128 + threadIdx.x;
  bool active = l < LJ;
  int nkeys = active ? ((l < LV) ? LV : (l + 1)) : 0;
  int lmax = min(blockIdx.x * 128 + 127, LJ - 1);
  int kmax = (lmax < LV) ? LV : (lmax + 1);   // 2048 or 2112, both %32==0

  __shared__ float4 Ks[32][16];
  __shared__ float4 Vs[32][16];

  float4 qr[16];
  if (active) {
    const float4* qp = (const float4*)(Q + ((size_t)(b * LJ + l)) * QN + h * HD);
    #pragma unroll
    for (int i = 0; i < 16; i++) {
      float4 t = qp[i];
      t.x *= SCALE; t.y *= SCALE; t.z *= SCALE; t.w *= SCALE;
      qr[i] = t;
    }
  }
  float4 acc[16];
  #pragma unroll
  for (int i = 0; i < 16; i++) acc[i] = make_float4(0.f, 0.f, 0.f, 0.f);
  float mi = -1e30f, li = 0.f;

  int t = threadIdx.x;
  int ldr = t >> 2;          // key row 0..31
  int ldc = (t & 3) * 4;     // float4 col base

  for (int k0 = 0; k0 < kmax; k0 += 32) {
    __syncthreads();
    const float4* kp = (const float4*)(Kb + ((size_t)(b * LJ + k0 + ldr)) * KVN + kvh * HD);
    const float4* vp = (const float4*)(Vb + ((size_t)(b * LJ + k0 + ldr)) * KVN + kvh * HD);
    #pragma unroll
    for (int u = 0; u < 4; u++) {
      Ks[ldr][ldc + u] = kp[ldc + u];
      Vs[ldr][ldc + u] = vp[ldc + u];
    }
    __syncthreads();
    if (!active) continue;

    float s[32];
    float tmax = -1e30f;
    #pragma unroll
    for (int j = 0; j < 32; j++) {
      float a0 = 0.f, a1 = 0.f, a2 = 0.f, a3 = 0.f;
      #pragma unroll
      for (int i = 0; i < 16; i++) {
        float4 kk = Ks[j][i];
        a0 += qr[i].x * kk.x;
        a1 += qr[i].y * kk.y;
        a2 += qr[i].z * kk.z;
        a3 += qr[i].w * kk.w;
      }
      float sj = ((k0 + j) < nkeys) ? ((a0 + a1) + (a2 + a3)) : -1e30f;
      s[j] = sj;
      tmax = fmaxf(tmax, sj);
    }
    float mnew = fmaxf(mi, tmax);
    float corr = __expf(mi - mnew);
    li *= corr;
    #pragma unroll
    for (int i = 0; i < 16; i++) {
      acc[i].x *= corr; acc[i].y *= corr; acc[i].z *= corr; acc[i].w *= corr;
    }
    #pragma unroll
    for (int j = 0; j < 32; j++) {
      float p = __expf(s[j] - mnew);
      li += p;
      #pragma unroll
      for (int i = 0; i < 16; i++) {
        float4 vv = Vs[j][i];
        acc[i].x += p * vv.x; acc[i].y += p * vv.y;
        acc[i].z += p * vv.z; acc[i].w += p * vv.w;
      }
    }
    mi = mnew;
  }

  if (active) {
    float inv = 1.f / li;
    float4* op = (float4*)(O + ((size_t)(b * LJ + l)) * QN + h * HD);
    #pragma unroll
    for (int i = 0; i < 16; i++) {
      float4 r = acc[i];
      r.x *= inv; r.y *= inv; r.z *= inv; r.w *= inv;
      op[i] = r;
    }
  }
}

// ---------------------------------------------------------------------------
// Launch
// ---------------------------------------------------------------------------
extern "C" void kernel_launch(void* const* d_in, const int* in_sizes, int n_in,
                              void* d_out, int out_size) {
  const float* hv  = (const float*)d_in[0];
  const float* he  = (const float*)d_in[1];
  const float* lnv = (const float*)d_in[2];
  const float* wqv = (const float*)d_in[3];
  const float* wkv = (const float*)d_in[4];
  const float* wvv = (const float*)d_in[5];
  const float* wov = (const float*)d_in[6];
  const float* lne = (const float*)d_in[7];
  const float* wqe = (const float*)d_in[8];
  const float* wke = (const float*)d_in[9];
  const float* wve = (const float*)d_in[10];
  const float* woe = (const float*)d_in[11];
  const int* pv = (const int*)d_in[12];
  const int* pe = (const int*)d_in[13];
  float* out = (float*)d_out;

  float *xnv, *xne, *q, *k, *v, *attn;
  cudaGetSymbolAddress((void**)&xnv, g_xn_v);
  cudaGetSymbolAddress((void**)&xne, g_xn_e);
  cudaGetSymbolAddress((void**)&q,   g_q);
  cudaGetSymbolAddress((void**)&k,   g_k);
  cudaGetSymbolAddress((void**)&v,   g_v);
  cudaGetSymbolAddress((void**)&attn, g_attn);

  // 1) RMSNorm both streams
  rmsnorm_kernel<<<NB * LV, 256>>>(hv, lnv, xnv);
  rmsnorm_kernel<<<NB * LE, 256>>>(he, lne, xne);

  // 2) QKV projections (scatter into joint [B, LJ, *] layout)
  sgemm_map<<<dim3(QN / 64,  (NB * LV) / 64), 256>>>(xnv, wqv, q, nullptr, NB * LV, QN,  DMODEL, LV, 0,  0);
  sgemm_map<<<dim3(KVN / 64, (NB * LV) / 64), 256>>>(xnv, wkv, k, nullptr, NB * LV, KVN, DMODEL, LV, 0,  0);
  sgemm_map<<<dim3(KVN / 64, (NB * LV) / 64), 256>>>(xnv, wvv, v, nullptr, NB * LV, KVN, DMODEL, LV, 0,  0);
  sgemm_map<<<dim3(QN / 64,  (NB * LE) / 64), 256>>>(xne, wqe, q, nullptr, NB * LE, QN,  DMODEL, LE, LV, 0);
  sgemm_map<<<dim3(KVN / 64, (NB * LE) / 64), 256>>>(xne, wke, k, nullptr, NB * LE, KVN, DMODEL, LE, LV, 0);
  sgemm_map<<<dim3(KVN / 64, (NB * LE) / 64), 256>>>(xne, wve, v, nullptr, NB * LE, KVN, DMODEL, LE, LV, 0);

  // 3) RoPE on q and k (in place)
  int pq = NB * LJ * NH;
  int pk = NB * LJ * NKVH;
  rope_kernel<<<(pq + 7) / 8, 256>>>(q, NH,   pq, pv, pe);
  rope_kernel<<<(pk + 7) / 8, 256>>>(k, NKVH, pk, pv, pe);

  // 4) Attention
  attn_kernel<<<dim3((LJ + 127) / 128, NH, NB), 128>>>(q, k, v, attn);

  // 5) Output projection + residual (gather joint A, scatter joint C)
  sgemm_map<<<dim3(QN / 64, (NB * LV) / 64), 256>>>(attn, wov, out, hv, NB * LV, QN, DMODEL, LV, 0,  1);
  sgemm_map<<<dim3(QN / 64, (NB * LE) / 64), 256>>>(attn, woe, out, he, NB * LE, QN, DMODEL, LE, LV, 1);
}

// round 3
// speedup vs baseline: 3.8952x; 3.8952x over previous
#include <cuda_runtime.h>
#include <math.h>
#include <stdint.h>

// Problem constants
#define NB 4
#define LV 2048
#define LE 64
#define LJ 2112        // LV + LE
#define DMODEL 960
#define NH 15
#define NKVH 5
#define HD 64
#define GQ 3           // NH / NKVH
#define QN (NH*HD)     // 960
#define KVN (NKVH*HD)  // 320
#define CEXP 0.18033688011112042f   // 0.125 * log2(e)

// Scratch (static device globals: allocation-free per harness rules)
__device__ float g_xn_v[NB*LV*DMODEL];
__device__ float g_xn_e[NB*LE*DMODEL];
__device__ float g_q[NB*LJ*QN];
__device__ float g_k[NB*LJ*KVN];
__device__ float g_v[NB*LJ*KVN];
__device__ float g_attn[NB*LJ*QN];
__device__ float g_w[4915200];   // tf32-rounded weights

// ---------------------------------------------------------------------------
// helpers
// ---------------------------------------------------------------------------
__device__ __forceinline__ uint32_t smem_u32(const void* p) {
  uint32_t a;
  asm("{ .reg .u64 t; cvta.to.shared.u64 t, %1; cvt.u32.u64 %0, t; }" : "=r"(a) : "l"(p));
  return a;
}
__device__ __forceinline__ uint32_t f2tf(float f) {
  uint32_t r;
  asm("cvt.rna.tf32.f32 %0, %1;" : "=r"(r) : "f"(f));
  return r;
}
__device__ __forceinline__ float tf32r(float f) { return __uint_as_float(f2tf(f)); }
__device__ __forceinline__ float ex2(float x) {
  float y;
  asm("ex2.approx.ftz.f32 %0, %1;" : "=f"(y) : "f"(x));
  return y;
}
__device__ __forceinline__ uint32_t lds32(uint32_t a) {
  uint32_t v;
  asm volatile("ld.shared.b32 %0, [%1];" : "=r"(v) : "r"(a));
  return v;
}
__device__ __forceinline__ void sts_v2(uint32_t a, float x, float y) {
  asm volatile("st.shared.v2.f32 [%0], {%1,%2};" :: "r"(a), "f"(x), "f"(y) : "memory");
}
__device__ __forceinline__ void cpa16(uint32_t dst, const void* src) {
  asm volatile("cp.async.cg.shared.global [%0], [%1], 16;" :: "r"(dst), "l"(src) : "memory");
}
#define CPA_COMMIT asm volatile("cp.async.commit_group;" ::: "memory")
#define CPA_WAIT0  asm volatile("cp.async.wait_group 0;" ::: "memory")

__device__ __forceinline__ void mma_tf32(float c[4], const uint32_t a[4],
                                         uint32_t b0, uint32_t b1) {
  asm volatile(
      "mma.sync.aligned.m16n8k8.row.col.f32.tf32.tf32.f32 "
      "{%0,%1,%2,%3}, {%4,%5,%6,%7}, {%8,%9}, {%0,%1,%2,%3};"
      : "+f"(c[0]), "+f"(c[1]), "+f"(c[2]), "+f"(c[3])
      : "r"(a[0]), "r"(a[1]), "r"(a[2]), "r"(a[3]), "r"(b0), "r"(b1));
}

// ---------------------------------------------------------------------------
// Weight convert: fp32 -> tf32-rounded fp32
// ---------------------------------------------------------------------------
__global__ void cvt_kernel(const float* __restrict__ src, float* __restrict__ dst, int n4) {
  int i = blockIdx.x * 256 + threadIdx.x;
  if (i < n4) {
    float4 v = ((const float4*)src)[i];
    v.x = tf32r(v.x); v.y = tf32r(v.y); v.z = tf32r(v.z); v.w = tf32r(v.w);
    ((float4*)dst)[i] = v;
  }
}

// ---------------------------------------------------------------------------
// RMSNorm (tf32-rounded output): one block per row, 256 threads over D=960
// ---------------------------------------------------------------------------
__global__ void rmsnorm_kernel(const float* __restrict__ x, const float* __restrict__ w,
                               float* __restrict__ out) {
  int row = blockIdx.x;
  const float* xr = x + (size_t)row * DMODEL;
  float* orow = out + (size_t)row * DMODEL;
  int t = threadIdx.x;
  float v[4];
  float ss = 0.f;
  #pragma unroll
  for (int i = 0; i < 4; i++) {
    int idx = t + i * 256;
    v[i] = (idx < DMODEL) ? xr[idx] : 0.f;
    ss += v[i] * v[i];
  }
  #pragma unroll
  for (int o = 16; o > 0; o >>= 1) ss += __shfl_xor_sync(0xffffffffu, ss, o);
  __shared__ float wsum[8];
  if ((t & 31) == 0) wsum[t >> 5] = ss;
  __syncthreads();
  if (t < 32) {
    float s = (t < 8) ? wsum[t] : 0.f;
    #pragma unroll
    for (int o = 4; o > 0; o >>= 1) s += __shfl_xor_sync(0xffffffffu, s, o);
    if (t == 0) wsum[0] = s;
  }
  __syncthreads();
  float rms = rsqrtf(wsum[0] * (1.f / DMODEL) + 1e-6f);
  #pragma unroll
  for (int i = 0; i < 4; i++) {
    int idx = t + i * 256;
    if (idx < DMODEL) orow[idx] = tf32r(v[i] * rms * w[idx]);
  }
}

// ---------------------------------------------------------------------------
// mma.sync tf32 GEMM. BM=128 BN=64 BK=32, 256 threads (8 warps, 4x2 grid,
// warp tile 32x32). cp.async double-buffered smem. Inputs pre-rounded to tf32.
// Joint-row mapping: m -> b=m/Lsrc, l=m%Lsrc, joint=b*LJ+l_off+l.
//   A row = a_joint ? joint : m (stride K); C row = joint (stride N);
//   resid indexed by m (stride N). rnd: tf32-round outputs.
// ---------------------------------------------------------------------------
#define GA_PITCH 36
#define GB_PITCH 72
#define GA_BYTES (128*GA_PITCH*4)   // 18432
#define GB_BYTES (32*GB_PITCH*4)    // 9216
#define GBUF (GA_BYTES+GB_BYTES)    // 27648
#define GEMM_SMEM (2*GBUF)          // 55296

__global__ void __launch_bounds__(256)
gemm_mma(const float* __restrict__ A, const float* __restrict__ W,
         float* __restrict__ C, const float* __restrict__ resid,
         int N, int K, int Lsrc, int l_off, int a_joint, int rnd) {
  extern __shared__ char sm[];
  uint32_t s0 = smem_u32(sm);
  int tid = threadIdx.x;
  int wid = tid >> 5, lane = tid & 31;
  int wm = wid >> 1, wn = wid & 1;
  int m0 = blockIdx.y * 128, n0 = blockIdx.x * 64;

  // cp.async assignments
  const float* asrc[4]; uint32_t adst[4];
  #pragma unroll
  for (int i = 0; i < 4; i++) {
    int idx = tid + 256 * i;
    int row = idx >> 3, c4 = idx & 7;
    int m = m0 + row;
    int grow = a_joint ? ((m / Lsrc) * LJ + l_off + (m % Lsrc)) : m;
    asrc[i] = A + (size_t)grow * K + c4 * 4;
    adst[i] = row * (GA_PITCH * 4) + c4 * 16;
  }
  const float* bsrc[2]; uint32_t bdst[2];
  #pragma unroll
  for (int i = 0; i < 2; i++) {
    int idx = tid + 256 * i;
    int kr = idx >> 4, c4 = idx & 15;
    bsrc[i] = W + (size_t)kr * N + n0 + c4 * 4;
    bdst[i] = GA_BYTES + kr * (GB_PITCH * 4) + c4 * 16;
  }

  float c[2][4][4];
  #pragma unroll
  for (int mt = 0; mt < 2; mt++)
    #pragma unroll
    for (int nt = 0; nt < 4; nt++)
      #pragma unroll
      for (int i = 0; i < 4; i++) c[mt][nt][i] = 0.f;

  int nK = K >> 5;
  // prologue: tile 0 -> buffer 0
  #pragma unroll
  for (int i = 0; i < 4; i++) cpa16(s0 + adst[i], asrc[i]);
  #pragma unroll
  for (int i = 0; i < 2; i++) cpa16(s0 + bdst[i], bsrc[i]);
  CPA_COMMIT;

  for (int it = 0; it < nK; it++) {
    CPA_WAIT0;
    __syncthreads();
    if (it + 1 < nK) {
      uint32_t boff = ((it + 1) & 1) * GBUF;
      int k0 = (it + 1) << 5;
      #pragma unroll
      for (int i = 0; i < 4; i++) cpa16(s0 + boff + adst[i], asrc[i] + k0);
      #pragma unroll
      for (int i = 0; i < 2; i++) cpa16(s0 + boff + bdst[i], bsrc[i] + (size_t)k0 * N);
      CPA_COMMIT;
    }
    uint32_t Ab = s0 + (it & 1) * GBUF;
    uint32_t Bb = Ab + GA_BYTES;
    int r0 = wm * 32 + (lane >> 2);
    #pragma unroll
    for (int kk = 0; kk < 4; kk++) {
      int kc = kk * 8 + (lane & 3);
      uint32_t a[2][4];
      #pragma unroll
      for (int mt = 0; mt < 2; mt++) {
        int r = r0 + mt * 16;
        a[mt][0] = lds32(Ab + (r * GA_PITCH + kc) * 4);
        a[mt][1] = lds32(Ab + ((r + 8) * GA_PITCH + kc) * 4);
        a[mt][2] = lds32(Ab + (r * GA_PITCH + kc + 4) * 4);
        a[mt][3] = lds32(Ab + ((r + 8) * GA_PITCH + kc + 4) * 4);
      }
      #pragma unroll
      for (int nt = 0; nt < 4; nt++) {
        int cn = wn * 32 + nt * 8 + (lane >> 2);
        uint32_t b0 = lds32(Bb + (kc * GB_PITCH + cn) * 4);
        uint32_t b1 = lds32(Bb + ((kc + 4) * GB_PITCH + cn) * 4);
        mma_tf32(c[0][nt], a[0], b0, b1);
        mma_tf32(c[1][nt], a[1], b0, b1);
      }
    }
  }

  // epilogue
  #pragma unroll
  for (int mt = 0; mt < 2; mt++) {
    #pragma unroll
    for (int hh = 0; hh < 2; hh++) {
      int m = m0 + wm * 32 + mt * 16 + (lane >> 2) + hh * 8;
      int cr = (m / Lsrc) * LJ + l_off + (m % Lsrc);
      #pragma unroll
      for (int nt = 0; nt < 4; nt++) {
        int cn = n0 + wn * 32 + nt * 8 + 2 * (lane & 3);
        float vx = c[mt][nt][2 * hh], vy = c[mt][nt][2 * hh + 1];
        if (resid) {
          float2 hv = *(const float2*)(resid + (size_t)m * N + cn);
          vx += hv.x; vy += hv.y;
        }
        if (rnd) { vx = tf32r(vx); vy = tf32r(vy); }
        float2 o; o.x = vx; o.y = vy;
        *(float2*)(C + (size_t)cr * N + cn) = o;
      }
    }
  }
}

// ---------------------------------------------------------------------------
// RoPE (in-place, tf32-rounded output)
// ---------------------------------------------------------------------------
__global__ void rope_kernel(float* __restrict__ buf, int nh, int npairs,
                            const int* __restrict__ pv, const int* __restrict__ pe) {
  int pair = blockIdx.x * 8 + (threadIdx.x >> 5);
  if (pair >= npairs) return;
  int j = threadIdx.x & 31;
  int h = pair % nh;
  int r = pair / nh;
  int b = r / LJ;
  int l = r - b * LJ;
  int pos = (l < LV) ? pv[b * LV + l] : pe[b * LE + (l - LV)];
  double dinv = exp((double)j * (-9.210340371976184 / 32.0));  // 10000^(-j/32)
  float rad = (float)((double)pos * dinv);
  float sn, cs;
  sincosf(rad, &sn, &cs);
  float* p = buf + (size_t)r * (nh * HD) + h * HD;
  float x1 = p[j];
  float x2 = p[j + 32];
  p[j] = tf32r(x1 * cs - x2 * sn);
  p[j + 32] = tf32r(x2 * cs + x1 * sn);
}

// ---------------------------------------------------------------------------
// Flash attention with mma.sync tf32.
// Block = 128 threads (4 warps), 64 q rows for (head h, batch b).
// Warp w owns q rows [16w, 16w+16). KV tiles of 64 keys, cp.async double-buffered.
// S = Q K^T via mma (Q frags register-resident); fp32 online softmax (scale in
// exponent); P staged through per-warp smem (tf32-rounded); O += P V via mma.
// ---------------------------------------------------------------------------
#define AQ_PITCH 68
#define AV_PITCH 72
#define AQ_BYTES (64*AQ_PITCH*4)   // 17408
#define AV_BYTES (64*AV_PITCH*4)   // 18432
#define AK_OFF(bb) (AQ_BYTES + (bb)*AQ_BYTES)
#define AV_OFF(bb) (3*AQ_BYTES + (bb)*AV_BYTES)
#define AP_OFF     (3*AQ_BYTES + 2*AV_BYTES)
#define AP_WARP    (16*AQ_PITCH*4)  // 4352
#define ATTN_SMEM  (AP_OFF + 4*AP_WARP)  // 106496

__global__ void __launch_bounds__(128)
attn_mma(const float* __restrict__ Qg, const float* __restrict__ Kg,
         const float* __restrict__ Vg, float* __restrict__ Og) {
  extern __shared__ char sm[];
  uint32_t s0 = smem_u32(sm);
  int tid = threadIdx.x;
  int wid = tid >> 5, lane = tid & 31;
  int bx = blockIdx.x, h = blockIdx.y, b = blockIdx.z;
  int kvh = h / GQ;
  int q0 = bx * 64;
  int nT = (q0 < LV) ? (LV / 64) : (LJ / 64);  // 32 or 33

  // cp.async chunk mapping (8 chunks per thread per tile)
  int crow[8], cc4[8];
  #pragma unroll
  for (int i = 0; i < 8; i++) {
    int idx = tid + 128 * i;
    crow[i] = idx >> 4;
    cc4[i] = idx & 15;
  }

  // prologue: Q + tile 0
  #pragma unroll
  for (int i = 0; i < 8; i++) {
    const float* src = Qg + ((size_t)(b * LJ + q0 + crow[i])) * QN + h * HD + cc4[i] * 4;
    cpa16(s0 + crow[i] * (AQ_PITCH * 4) + cc4[i] * 16, src);
  }
  #pragma unroll
  for (int i = 0; i < 8; i++) {
    const float* ks = Kg + ((size_t)(b * LJ + crow[i])) * KVN + kvh * HD + cc4[i] * 4;
    const float* vs = Vg + ((size_t)(b * LJ + crow[i])) * KVN + kvh * HD + cc4[i] * 4;
    cpa16(s0 + AK_OFF(0) + crow[i] * (AQ_PITCH * 4) + cc4[i] * 16, ks);
    cpa16(s0 + AV_OFF(0) + crow[i] * (AV_PITCH * 4) + cc4[i] * 16, vs);
  }
  CPA_COMMIT;

  float o[8][4];
  #pragma unroll
  for (int nt = 0; nt < 8; nt++)
    #pragma unroll
    for (int i = 0; i < 4; i++) o[nt][i] = 0.f;
  float mi0 = -1e30f, mi1 = -1e30f, li0 = 0.f, li1 = 0.f;

  uint32_t qf[8][4];
  uint32_t Pb = s0 + AP_OFF + wid * AP_WARP;
  int r0 = lane >> 2;          // local row 0..7
  int kc0 = 2 * (lane & 3);

  for (int it = 0; it < nT; it++) {
    CPA_WAIT0;
    __syncthreads();
    if (it + 1 < nT) {
      uint32_t kb = AK_OFF((it + 1) & 1), vb = AV_OFF((it + 1) & 1);
      int krow0 = (it + 1) * 64;
      #pragma unroll
      for (int i = 0; i < 8; i++) {
        const float* ks = Kg + ((size_t)(b * LJ + krow0 + crow[i])) * KVN + kvh * HD + cc4[i] * 4;
        const float* vs = Vg + ((size_t)(b * LJ + krow0 + crow[i])) * KVN + kvh * HD + cc4[i] * 4;
        cpa16(s0 + kb + crow[i] * (AQ_PITCH * 4) + cc4[i] * 16, ks);
        cpa16(s0 + vb + crow[i] * (AV_PITCH * 4) + cc4[i] * 16, vs);
      }
      CPA_COMMIT;
    }
    if (it == 0) {
      // load Q fragments (rows wid*16 + r0 / +8)
      int qr = wid * 16 + r0;
      #pragma unroll
      for (int kk = 0; kk < 8; kk++) {
        int kc = kk * 8 + (lane & 3);
        qf[kk][0] = lds32(s0 + (qr * AQ_PITCH + kc) * 4);
        qf[kk][1] = lds32(s0 + ((qr + 8) * AQ_PITCH + kc) * 4);
        qf[kk][2] = lds32(s0 + (qr * AQ_PITCH + kc + 4) * 4);
        qf[kk][3] = lds32(s0 + ((qr + 8) * AQ_PITCH + kc + 4) * 4);
      }
    }

    // ---- S = Q K^T ----
    uint32_t Kb = s0 + AK_OFF(it & 1);
    float s[8][4];
    #pragma unroll
    for (int nt = 0; nt < 8; nt++) {
      s[nt][0] = s[nt][1] = s[nt][2] = s[nt][3] = 0.f;
      int cn = nt * 8 + (lane >> 2);
      #pragma unroll
      for (int kk = 0; kk < 8; kk++) {
        int kc = kk * 8 + (lane & 3);
        uint32_t b0 = lds32(Kb + (cn * AQ_PITCH + kc) * 4);
        uint32_t b1 = lds32(Kb + (cn * AQ_PITCH + kc + 4) * 4);
        mma_tf32(s[nt], qf[kk], b0, b1);
      }
    }

    // causal mask (only expert q-tile, last KV tile)
    if (q0 >= LV && it == (LJ / 64 - 1)) {
      int rl = wid * 16 + r0;
      #pragma unroll
      for (int nt = 0; nt < 8; nt++) {
        int kc = nt * 8 + kc0;
        if (kc > rl)         s[nt][0] = -1e30f;
        if (kc + 1 > rl)     s[nt][1] = -1e30f;
        if (kc > rl + 8)     s[nt][2] = -1e30f;
        if (kc + 1 > rl + 8) s[nt][3] = -1e30f;
      }
    }

    // ---- online softmax ----
    float tm0 = -1e30f, tm1 = -1e30f;
    #pragma unroll
    for (int nt = 0; nt < 8; nt++) {
      tm0 = fmaxf(tm0, fmaxf(s[nt][0], s[nt][1]));
      tm1 = fmaxf(tm1, fmaxf(s[nt][2], s[nt][3]));
    }
    tm0 = fmaxf(tm0, __shfl_xor_sync(0xffffffffu, tm0, 1));
    tm0 = fmaxf(tm0, __shfl_xor_sync(0xffffffffu, tm0, 2));
    tm1 = fmaxf(tm1, __shfl_xor_sync(0xffffffffu, tm1, 1));
    tm1 = fmaxf(tm1, __shfl_xor_sync(0xffffffffu, tm1, 2));
    float mn0 = fmaxf(mi0, tm0), mn1 = fmaxf(mi1, tm1);
    float cr0 = ex2((mi0 - mn0) * CEXP), cr1 = ex2((mi1 - mn1) * CEXP);
    li0 *= cr0; li1 *= cr1;
    #pragma unroll
    for (int nt = 0; nt < 8; nt++) {
      o[nt][0] *= cr0; o[nt][1] *= cr0; o[nt][2] *= cr1; o[nt][3] *= cr1;
    }
    #pragma unroll
    for (int nt = 0; nt < 8; nt++) {
      float p0 = ex2((s[nt][0] - mn0) * CEXP);
      float p1 = ex2((s[nt][1] - mn0) * CEXP);
      float p2 = ex2((s[nt][2] - mn1) * CEXP);
      float p3 = ex2((s[nt][3] - mn1) * CEXP);
      p0 = tf32r(p0); p1 = tf32r(p1); p2 = tf32r(p2); p3 = tf32r(p3);
      li0 += p0 + p1;
      li1 += p2 + p3;
      int kc = nt * 8 + kc0;
      sts_v2(Pb + (r0 * AQ_PITCH + kc) * 4, p0, p1);
      sts_v2(Pb + ((r0 + 8) * AQ_PITCH + kc) * 4, p2, p3);
    }
    mi0 = mn0; mi1 = mn1;
    __syncwarp();

    // ---- O += P V ----
    uint32_t Vb = s0 + AV_OFF(it & 1);
    #pragma unroll
    for (int kk = 0; kk < 8; kk++) {
      int kc = kk * 8 + (lane & 3);
      uint32_t a[4];
      a[0] = lds32(Pb + (r0 * AQ_PITCH + kc) * 4);
      a[1] = lds32(Pb + ((r0 + 8) * AQ_PITCH + kc) * 4);
      a[2] = lds32(Pb + (r0 * AQ_PITCH + kc + 4) * 4);
      a[3] = lds32(Pb + ((r0 + 8) * AQ_PITCH + kc + 4) * 4);
      #pragma unroll
      for (int nt = 0; nt < 8; nt++) {
        int cn = nt * 8 + (lane >> 2);
        uint32_t b0 = lds32(Vb + (kc * AV_PITCH + cn) * 4);
        uint32_t b1 = lds32(Vb + ((kc + 4) * AV_PITCH + cn) * 4);
        mma_tf32(o[nt], a, b0, b1);
      }
    }
    __syncwarp();
  }

  // finalize
  li0 += __shfl_xor_sync(0xffffffffu, li0, 1);
  li0 += __shfl_xor_sync(0xffffffffu, li0, 2);
  li1 += __shfl_xor_sync(0xffffffffu, li1, 1);
  li1 += __shfl_xor_sync(0xffffffffu, li1, 2);
  float inv0 = 1.f / li0, inv1 = 1.f / li1;
  int gr0 = b * LJ + q0 + wid * 16 + r0;
  #pragma unroll
  for (int nt = 0; nt < 8; nt++) {
    int cn = h * HD + nt * 8 + kc0;
    float2 v0, v1;
    v0.x = tf32r(o[nt][0] * inv0); v0.y = tf32r(o[nt][1] * inv0);
    v1.x = tf32r(o[nt][2] * inv1); v1.y = tf32r(o[nt][3] * inv1);
    *(float2*)(Og + (size_t)gr0 * QN + cn) = v0;
    *(float2*)(Og + (size_t)(gr0 + 8) * QN + cn) = v1;
  }
}

// ---------------------------------------------------------------------------
// Launch
// ---------------------------------------------------------------------------
extern "C" void kernel_launch(void* const* d_in, const int* in_sizes, int n_in,
                              void* d_out, int out_size) {
  const float* hv  = (const float*)d_in[0];
  const float* he  = (const float*)d_in[1];
  const float* lnv = (const float*)d_in[2];
  const float* wqv = (const float*)d_in[3];
  const float* wkv = (const float*)d_in[4];
  const float* wvv = (const float*)d_in[5];
  const float* wov = (const float*)d_in[6];
  const float* lne = (const float*)d_in[7];
  const float* wqe = (const float*)d_in[8];
  const float* wke = (const float*)d_in[9];
  const float* wve = (const float*)d_in[10];
  const float* woe = (const float*)d_in[11];
  const int* pv = (const int*)d_in[12];
  const int* pe = (const int*)d_in[13];
  float* out = (float*)d_out;

  float *xnv, *xne, *q, *k, *v, *attn, *w;
  cudaGetSymbolAddress((void**)&xnv, g_xn_v);
  cudaGetSymbolAddress((void**)&xne, g_xn_e);
  cudaGetSymbolAddress((void**)&q,   g_q);
  cudaGetSymbolAddress((void**)&k,   g_k);
  cudaGetSymbolAddress((void**)&v,   g_v);
  cudaGetSymbolAddress((void**)&attn, g_attn);
  cudaGetSymbolAddress((void**)&w,   g_w);

  cudaFuncSetAttribute(gemm_mma, cudaFuncAttributeMaxDynamicSharedMemorySize, GEMM_SMEM);
  cudaFuncSetAttribute(attn_mma, cudaFuncAttributeMaxDynamicSharedMemorySize, ATTN_SMEM);

  // weight offsets in g_w
  const int SQ = 960 * 960, SK = 960 * 320;
  float* cwqv = w;
  float* cwkv = w + SQ;
  float* cwvv = w + SQ + SK;
  float* cwov = w + SQ + 2 * SK;
  float* cwqe = w + 2 * SQ + 2 * SK;
  float* cwke = w + 3 * SQ + 2 * SK;
  float* cwve = w + 3 * SQ + 3 * SK;
  float* cwoe = w + 3 * SQ + 4 * SK;

  cvt_kernel<<<SQ / 1024, 256>>>(wqv, cwqv, SQ / 4);
  cvt_kernel<<<SK / 1024, 256>>>(wkv, cwkv, SK / 4);
  cvt_kernel<<<SK / 1024, 256>>>(wvv, cwvv, SK / 4);
  cvt_kernel<<<SQ / 1024, 256>>>(wov, cwov, SQ / 4);
  cvt_kernel<<<SQ / 1024, 256>>>(wqe, cwqe, SQ / 4);
  cvt_kernel<<<SK / 1024, 256>>>(wke, cwke, SK / 4);
  cvt_kernel<<<SK / 1024, 256>>>(wve, cwve, SK / 4);
  cvt_kernel<<<SQ / 1024, 256>>>(woe, cwoe, SQ / 4);

  // 1) RMSNorm (tf32-rounded outputs)
  rmsnorm_kernel<<<NB * LV, 256>>>(hv, lnv, xnv);
  rmsnorm_kernel<<<NB * LE, 256>>>(he, lne, xne);

  // 2) QKV projections (V rounds its output; Q/K rounded later by rope)
  gemm_mma<<<dim3(QN / 64,  (NB * LV) / 128), 256, GEMM_SMEM>>>(xnv, cwqv, q, nullptr, QN,  DMODEL, LV, 0,  0, 0);
  gemm_mma<<<dim3(KVN / 64, (NB * LV) / 128), 256, GEMM_SMEM>>>(xnv, cwkv, k, nullptr, KVN, DMODEL, LV, 0,  0, 0);
  gemm_mma<<<dim3(KVN / 64, (NB * LV) / 128), 256, GEMM_SMEM>>>(xnv, cwvv, v, nullptr, KVN, DMODEL, LV, 0,  0, 1);
  gemm_mma<<<dim3(QN / 64,  (NB * LE) / 128), 256, GEMM_SMEM>>>(xne, cwqe, q, nullptr, QN,  DMODEL, LE, LV, 0, 0);
  gemm_mma<<<dim3(KVN / 64, (NB * LE) / 128), 256, GEMM_SMEM>>>(xne, cwke, k, nullptr, KVN, DMODEL, LE, LV, 0, 0);
  gemm_mma<<<dim3(KVN / 64, (NB * LE) / 128), 256, GEMM_SMEM>>>(xne, cwve, v, nullptr, KVN, DMODEL, LE, LV, 0, 1);

  // 3) RoPE on q and k (in place, tf32-rounded)
  int pq = NB * LJ * NH;
  int pk = NB * LJ * NKVH;
  rope_kernel<<<(pq + 7) / 8, 256>>>(q, NH,   pq, pv, pe);
  rope_kernel<<<(pk + 7) / 8, 256>>>(k, NKVH, pk, pv, pe);

  // 4) Attention (tensor-core)
  attn_mma<<<dim3(LJ / 64, NH, NB), 128, ATTN_SMEM>>>(q, k, v, attn);

  // 5) Output projection + residual
  gemm_mma<<<dim3(QN / 64, (NB * LV) / 128), 256, GEMM_SMEM>>>(attn, cwov, out, hv, QN, DMODEL, LV, 0,  1, 0);
  gemm_mma<<<dim3(QN / 64, (NB * LE) / 128), 256, GEMM_SMEM>>>(attn, cwoe, out, he, QN, DMODEL, LE, LV, 1, 0);
}

// round 4
// speedup vs baseline: 6.1553x; 1.5802x over previous
#include <cuda_runtime.h>
#include <cuda_bf16.h>
#include <math.h>
#include <stdint.h>

// Problem constants
#define NB 4
#define LV 2048
#define LE 64
#define LJ 2112        // LV + LE
#define DMODEL 960
#define NH 15
#define NKVH 5
#define HD 64
#define GQ 3           // NH / NKVH
#define QN (NH*HD)     // 960
#define KVN (NKVH*HD)  // 320
#define CEXP 0.18033688011112042f   // 0.125 * log2(e)

typedef __nv_bfloat16 bf16;

// Scratch (static device globals: allocation-free per harness rules)
__device__ bf16 g_xh_v[NB*LV*DMODEL];
__device__ bf16 g_xh_e[NB*LE*DMODEL];
__device__ bf16 g_qh[NB*LJ*QN];
__device__ bf16 g_kh[NB*LJ*KVN];
__device__ bf16 g_vt[NB*KVN*LJ];      // [b][kvh][d][l] transposed V
__device__ bf16 g_attn[NB*LJ*QN];
__device__ bf16 g_wh[4915200];        // bf16 transposed weights

// ---------------------------------------------------------------------------
// helpers
// ---------------------------------------------------------------------------
__device__ __forceinline__ uint32_t smem_u32(const void* p) {
  uint32_t a;
  asm("{ .reg .u64 t; cvta.to.shared.u64 t, %1; cvt.u32.u64 %0, t; }" : "=r"(a) : "l"(p));
  return a;
}
__device__ __forceinline__ float ex2(float x) {
  float y;
  asm("ex2.approx.ftz.f32 %0, %1;" : "=f"(y) : "f"(x));
  return y;
}
__device__ __forceinline__ uint32_t lds32(uint32_t a) {
  uint32_t v;
  asm volatile("ld.shared.b32 %0, [%1];" : "=r"(v) : "r"(a));
  return v;
}
__device__ __forceinline__ void sts32(uint32_t a, uint32_t v) {
  asm volatile("st.shared.b32 [%0], %1;" :: "r"(a), "r"(v) : "memory");
}
__device__ __forceinline__ void cpa16(uint32_t dst, const void* src) {
  asm volatile("cp.async.cg.shared.global [%0], [%1], 16;" :: "r"(dst), "l"(src) : "memory");
}
#define CPA_COMMIT asm volatile("cp.async.commit_group;" ::: "memory")
#define CPA_WAIT0  asm volatile("cp.async.wait_group 0;" ::: "memory")

__device__ __forceinline__ uint32_t packbf(float x, float y) {
  __nv_bfloat162 h = __floats2bfloat162_rn(x, y);
  return *(uint32_t*)&h;
}

__device__ __forceinline__ void mma_bf16(float c[4], const uint32_t a[4],
                                         uint32_t b0, uint32_t b1) {
  asm volatile(
      "mma.sync.aligned.m16n8k16.row.col.f32.bf16.bf16.f32 "
      "{%0,%1,%2,%3}, {%4,%5,%6,%7}, {%8,%9}, {%0,%1,%2,%3};"
      : "+f"(c[0]), "+f"(c[1]), "+f"(c[2]), "+f"(c[3])
      : "r"(a[0]), "r"(a[1]), "r"(a[2]), "r"(a[3]), "r"(b0), "r"(b1));
}

// ---------------------------------------------------------------------------
// Weight transpose+convert: W fp32 [K][N] -> Wt bf16 [N][K]
// ---------------------------------------------------------------------------
__global__ void cvt_t(const float* __restrict__ W, bf16* __restrict__ Wt, int K, int N) {
  __shared__ float t[32][33];
  int n0 = blockIdx.x * 32, k0 = blockIdx.y * 32;
  int tx = threadIdx.x, ty = threadIdx.y;
  #pragma unroll
  for (int i = 0; i < 4; i++)
    t[ty + i * 8][tx] = W[(size_t)(k0 + ty + i * 8) * N + n0 + tx];
  __syncthreads();
  #pragma unroll
  for (int i = 0; i < 4; i++)
    Wt[(size_t)(n0 + ty + i * 8) * K + k0 + tx] = __float2bfloat16_rn(t[tx][ty + i * 8]);
}

// ---------------------------------------------------------------------------
// RMSNorm (bf16 output): one block per row, 256 threads over D=960
// ---------------------------------------------------------------------------
__global__ void rmsnorm_kernel(const float* __restrict__ x, const float* __restrict__ w,
                               bf16* __restrict__ out) {
  int row = blockIdx.x;
  const float* xr = x + (size_t)row * DMODEL;
  bf16* orow = out + (size_t)row * DMODEL;
  int t = threadIdx.x;
  float v[4];
  float ss = 0.f;
  #pragma unroll
  for (int i = 0; i < 4; i++) {
    int idx = t + i * 256;
    v[i] = (idx < DMODEL) ? xr[idx] : 0.f;
    ss += v[i] * v[i];
  }
  #pragma unroll
  for (int o = 16; o > 0; o >>= 1) ss += __shfl_xor_sync(0xffffffffu, ss, o);
  __shared__ float wsum[8];
  if ((t & 31) == 0) wsum[t >> 5] = ss;
  __syncthreads();
  if (t < 32) {
    float s = (t < 8) ? wsum[t] : 0.f;
    #pragma unroll
    for (int o = 4; o > 0; o >>= 1) s += __shfl_xor_sync(0xffffffffu, s, o);
    if (t == 0) wsum[0] = s;
  }
  __syncthreads();
  float rms = rsqrtf(wsum[0] * (1.f / DMODEL) + 1e-6f);
  #pragma unroll
  for (int i = 0; i < 4; i++) {
    int idx = t + i * 256;
    if (idx < DMODEL) orow[idx] = __float2bfloat16_rn(v[i] * rms * w[idx]);
  }
}

// ---------------------------------------------------------------------------
// bf16 mma GEMM. BM=256 BN=64 BK=64, 256 threads (8 warps 4x2, warp tile
// 64x32). cp.async double-buffered. Wt is [N][K] bf16 (pre-transposed).
// Joint-row mapping: m -> b=m/Lsrc, l=m%Lsrc, joint=b*LJ+l_off+l.
// mode 0: bf16 out, joint scatter (Q/K pre-rope)
// mode 1: fp32 out + resid (indexed by m), joint scatter (O-proj)
// mode 2: bf16 transposed V out: g_vt[((b*NKVH+kvh)*HD+d)*LJ+l]
// ---------------------------------------------------------------------------
#define GBM 256
#define GPITCH 72
#define GABYTES (GBM*GPITCH*2)   // 36864
#define GBBYTES (64*GPITCH*2)    // 9216
#define GBUF (GABYTES+GBBYTES)   // 46080
#define GEMM_SMEM (2*GBUF)       // 92160

__global__ void __launch_bounds__(256)
gemm_bf16(const bf16* __restrict__ A, const bf16* __restrict__ Wt,
          float* __restrict__ Cf, bf16* __restrict__ Cb,
          const float* __restrict__ resid,
          int N, int K, int Lsrc, int l_off, int a_joint, int mode) {
  extern __shared__ char sm[];
  uint32_t s0 = smem_u32(sm);
  int tid = threadIdx.x;
  int wid = tid >> 5, lane = tid & 31;
  int wm = wid >> 1, wn = wid & 1;
  int m0 = blockIdx.y * GBM, n0 = blockIdx.x * 64;

  // cp.async assignments: A 8 chunks, B 2 chunks per thread
  const bf16* asrc[8]; uint32_t adst[8];
  #pragma unroll
  for (int i = 0; i < 8; i++) {
    int idx = tid + 256 * i;
    int row = idx >> 3, ch = idx & 7;
    int m = m0 + row;
    int grow = a_joint ? ((m / Lsrc) * LJ + l_off + (m % Lsrc)) : m;
    asrc[i] = A + (size_t)grow * K + ch * 8;
    adst[i] = row * (GPITCH * 2) + ch * 16;
  }
  const bf16* bsrc[2]; uint32_t bdst[2];
  #pragma unroll
  for (int i = 0; i < 2; i++) {
    int idx = tid + 256 * i;
    int row = idx >> 3, ch = idx & 7;
    bsrc[i] = Wt + (size_t)(n0 + row) * K + ch * 8;
    bdst[i] = GABYTES + row * (GPITCH * 2) + ch * 16;
  }

  float c[4][4][4];
  #pragma unroll
  for (int mt = 0; mt < 4; mt++)
    #pragma unroll
    for (int nt = 0; nt < 4; nt++)
      #pragma unroll
      for (int i = 0; i < 4; i++) c[mt][nt][i] = 0.f;

  int nK = K >> 6;   // 15
  #pragma unroll
  for (int i = 0; i < 8; i++) cpa16(s0 + adst[i], asrc[i]);
  #pragma unroll
  for (int i = 0; i < 2; i++) cpa16(s0 + bdst[i], bsrc[i]);
  CPA_COMMIT;

  for (int it = 0; it < nK; it++) {
    CPA_WAIT0;
    __syncthreads();
    if (it + 1 < nK) {
      uint32_t boff = ((it + 1) & 1) * GBUF;
      int k0 = (it + 1) << 6;
      #pragma unroll
      for (int i = 0; i < 8; i++) cpa16(s0 + boff + adst[i], asrc[i] + k0);
      #pragma unroll
      for (int i = 0; i < 2; i++) cpa16(s0 + boff + bdst[i], bsrc[i] + k0);
      CPA_COMMIT;
    }
    uint32_t Ab = s0 + (it & 1) * GBUF;
    uint32_t Bb = Ab + GABYTES;
    int rb = wm * 64 + (lane >> 2);
    #pragma unroll
    for (int kk = 0; kk < 4; kk++) {
      int kc = kk * 16 + 2 * (lane & 3);
      uint32_t a[4][4];
      #pragma unroll
      for (int mt = 0; mt < 4; mt++) {
        int r = rb + mt * 16;
        a[mt][0] = lds32(Ab + r * (GPITCH * 2) + kc * 2);
        a[mt][1] = lds32(Ab + (r + 8) * (GPITCH * 2) + kc * 2);
        a[mt][2] = lds32(Ab + r * (GPITCH * 2) + (kc + 8) * 2);
        a[mt][3] = lds32(Ab + (r + 8) * (GPITCH * 2) + (kc + 8) * 2);
      }
      #pragma unroll
      for (int nt = 0; nt < 4; nt++) {
        int n = wn * 32 + nt * 8 + (lane >> 2);
        uint32_t b0 = lds32(Bb + n * (GPITCH * 2) + kc * 2);
        uint32_t b1 = lds32(Bb + n * (GPITCH * 2) + (kc + 8) * 2);
        #pragma unroll
        for (int mt = 0; mt < 4; mt++) mma_bf16(c[mt][nt], a[mt], b0, b1);
      }
    }
  }

  // epilogue
  #pragma unroll
  for (int mt = 0; mt < 4; mt++) {
    #pragma unroll
    for (int hh = 0; hh < 2; hh++) {
      int m = m0 + wm * 64 + mt * 16 + (lane >> 2) + hh * 8;
      int bb = m / Lsrc, ll = m % Lsrc;
      int cr = bb * LJ + l_off + ll;
      #pragma unroll
      for (int nt = 0; nt < 4; nt++) {
        int cn = n0 + wn * 32 + nt * 8 + 2 * (lane & 3);
        float vx = c[mt][nt][2 * hh], vy = c[mt][nt][2 * hh + 1];
        if (mode == 0) {
          *(uint32_t*)(Cb + (size_t)cr * N + cn) = packbf(vx, vy);
        } else if (mode == 1) {
          float2 hv = *(const float2*)(resid + (size_t)m * N + cn);
          float2 o; o.x = vx + hv.x; o.y = vy + hv.y;
          *(float2*)(Cf + (size_t)cr * N + cn) = o;
        } else {
          int kvh = cn >> 6, d = cn & 63;
          size_t base = ((size_t)(bb * NKVH + kvh) * HD);
          Cb[(base + d) * LJ + l_off + ll] = __float2bfloat16_rn(vx);
          Cb[(base + d + 1) * LJ + l_off + ll] = __float2bfloat16_rn(vy);
        }
      }
    }
  }
}

// ---------------------------------------------------------------------------
// RoPE (in-place on bf16): one 32-thread group per (joint_row, head)
// ---------------------------------------------------------------------------
__global__ void rope_kernel(bf16* __restrict__ buf, int nh, int npairs,
                            const int* __restrict__ pv, const int* __restrict__ pe) {
  int pair = blockIdx.x * 8 + (threadIdx.x >> 5);
  if (pair >= npairs) return;
  int j = threadIdx.x & 31;
  int h = pair % nh;
  int r = pair / nh;
  int b = r / LJ;
  int l = r - b * LJ;
  int pos = (l < LV) ? pv[b * LV + l] : pe[b * LE + (l - LV)];
  double dinv = exp((double)j * (-9.210340371976184 / 32.0));  // 10000^(-j/32)
  float rad = (float)((double)pos * dinv);
  float sn, cs;
  sincosf(rad, &sn, &cs);
  bf16* p = buf + (size_t)r * (nh * HD) + h * HD;
  float x1 = __bfloat162float(p[j]);
  float x2 = __bfloat162float(p[j + 32]);
  p[j] = __float2bfloat16_rn(x1 * cs - x2 * sn);
  p[j + 32] = __float2bfloat16_rn(x2 * cs + x1 * sn);
}

// ---------------------------------------------------------------------------
// Flash attention, bf16 mma. Block = 128 threads (4 warps), 64 q rows for
// (head h, batch b). Warp w owns rows [16w,16w+16). 64-key KV tiles,
// cp.async double-buffered. V is pre-transposed [d][l]. P via per-warp smem.
// ---------------------------------------------------------------------------
#define APITCH 72
#define ATBYTES (64*APITCH*2)     // 9216
#define AK_OFF(bb) (ATBYTES + (bb)*ATBYTES)
#define AV_OFF(bb) (3*ATBYTES + (bb)*ATBYTES)
#define AP_OFF     (5*ATBYTES)
#define AP_WARP    (16*APITCH*2)  // 2304
#define ATTN_SMEM  (AP_OFF + 4*AP_WARP)  // 55296

__global__ void __launch_bounds__(128)
attn_mma(const bf16* __restrict__ Qg, const bf16* __restrict__ Kg,
         const bf16* __restrict__ Vt, bf16* __restrict__ Og) {
  extern __shared__ char sm[];
  uint32_t s0 = smem_u32(sm);
  int tid = threadIdx.x;
  int wid = tid >> 5, lane = tid & 31;
  int bx = blockIdx.x, h = blockIdx.y, b = blockIdx.z;
  int kvh = h / GQ;
  int q0 = bx * 64;
  int nT = (q0 < LV) ? (LV / 64) : (LJ / 64);  // 32 or 33

  // cp.async chunk mapping: 512 chunks per tile / 128 threads = 4 per thread
  int crow[4], cch[4];
  #pragma unroll
  for (int i = 0; i < 4; i++) {
    int idx = tid + 128 * i;
    crow[i] = idx >> 3;
    cch[i] = idx & 7;
  }
  const bf16* vbase = Vt + (size_t)(b * NKVH + kvh) * HD * LJ;

  // prologue: Q + tile 0
  #pragma unroll
  for (int i = 0; i < 4; i++) {
    const bf16* src = Qg + ((size_t)(b * LJ + q0 + crow[i])) * QN + h * HD + cch[i] * 8;
    cpa16(s0 + crow[i] * (APITCH * 2) + cch[i] * 16, src);
  }
  #pragma unroll
  for (int i = 0; i < 4; i++) {
    const bf16* ks = Kg + ((size_t)(b * LJ + crow[i])) * KVN + kvh * HD + cch[i] * 8;
    const bf16* vs = vbase + (size_t)crow[i] * LJ + cch[i] * 8;
    cpa16(s0 + AK_OFF(0) + crow[i] * (APITCH * 2) + cch[i] * 16, ks);
    cpa16(s0 + AV_OFF(0) + crow[i] * (APITCH * 2) + cch[i] * 16, vs);
  }
  CPA_COMMIT;

  float o[8][4];
  #pragma unroll
  for (int nt = 0; nt < 8; nt++)
    #pragma unroll
    for (int i = 0; i < 4; i++) o[nt][i] = 0.f;
  float mi0 = -1e30f, mi1 = -1e30f, li0 = 0.f, li1 = 0.f;

  uint32_t qf[4][4];
  uint32_t Pb = s0 + AP_OFF + wid * AP_WARP;
  int r0 = lane >> 2;
  int kc0 = 2 * (lane & 3);

  for (int it = 0; it < nT; it++) {
    CPA_WAIT0;
    __syncthreads();
    if (it + 1 < nT) {
      uint32_t kb = AK_OFF((it + 1) & 1), vb = AV_OFF((it + 1) & 1);
      int kr0 = (it + 1) * 64;
      #pragma unroll
      for (int i = 0; i < 4; i++) {
        const bf16* ks = Kg + ((size_t)(b * LJ + kr0 + crow[i])) * KVN + kvh * HD + cch[i] * 8;
        const bf16* vs = vbase + (size_t)crow[i] * LJ + kr0 + cch[i] * 8;
        cpa16(s0 + kb + crow[i] * (APITCH * 2) + cch[i] * 16, ks);
        cpa16(s0 + vb + crow[i] * (APITCH * 2) + cch[i] * 16, vs);
      }
      CPA_COMMIT;
    }
    if (it == 0) {
      int qr = wid * 16 + r0;
      #pragma unroll
      for (int kk = 0; kk < 4; kk++) {
        int kc = kk * 16 + kc0;
        qf[kk][0] = lds32(s0 + qr * (APITCH * 2) + kc * 2);
        qf[kk][1] = lds32(s0 + (qr + 8) * (APITCH * 2) + kc * 2);
        qf[kk][2] = lds32(s0 + qr * (APITCH * 2) + (kc + 8) * 2);
        qf[kk][3] = lds32(s0 + (qr + 8) * (APITCH * 2) + (kc + 8) * 2);
      }
    }

    // ---- S = Q K^T ----
    uint32_t Kb = s0 + AK_OFF(it & 1);
    float s[8][4];
    #pragma unroll
    for (int nt = 0; nt < 8; nt++) {
      s[nt][0] = s[nt][1] = s[nt][2] = s[nt][3] = 0.f;
      int key = nt * 8 + r0;
      #pragma unroll
      for (int kk = 0; kk < 4; kk++) {
        int kc = kk * 16 + kc0;
        uint32_t b0 = lds32(Kb + key * (APITCH * 2) + kc * 2);
        uint32_t b1 = lds32(Kb + key * (APITCH * 2) + (kc + 8) * 2);
        mma_bf16(s[nt], qf[kk], b0, b1);
      }
    }

    // causal mask (expert q-tile, last KV tile only)
    if (q0 >= LV && it == nT - 1) {
      int rl = wid * 16 + r0;
      #pragma unroll
      for (int nt = 0; nt < 8; nt++) {
        int kc = nt * 8 + kc0;
        if (kc > rl)         s[nt][0] = -1e30f;
        if (kc + 1 > rl)     s[nt][1] = -1e30f;
        if (kc > rl + 8)     s[nt][2] = -1e30f;
        if (kc + 1 > rl + 8) s[nt][3] = -1e30f;
      }
    }

    // ---- online softmax ----
    float tm0 = -1e30f, tm1 = -1e30f;
    #pragma unroll
    for (int nt = 0; nt < 8; nt++) {
      tm0 = fmaxf(tm0, fmaxf(s[nt][0], s[nt][1]));
      tm1 = fmaxf(tm1, fmaxf(s[nt][2], s[nt][3]));
    }
    tm0 = fmaxf(tm0, __shfl_xor_sync(0xffffffffu, tm0, 1));
    tm0 = fmaxf(tm0, __shfl_xor_sync(0xffffffffu, tm0, 2));
    tm1 = fmaxf(tm1, __shfl_xor_sync(0xffffffffu, tm1, 1));
    tm1 = fmaxf(tm1, __shfl_xor_sync(0xffffffffu, tm1, 2));
    float mn0 = fmaxf(mi0, tm0), mn1 = fmaxf(mi1, tm1);
    float cr0 = ex2((mi0 - mn0) * CEXP), cr1 = ex2((mi1 - mn1) * CEXP);
    li0 *= cr0; li1 *= cr1;
    #pragma unroll
    for (int nt = 0; nt < 8; nt++) {
      o[nt][0] *= cr0; o[nt][1] *= cr0; o[nt][2] *= cr1; o[nt][3] *= cr1;
    }
    #pragma unroll
    for (int nt = 0; nt < 8; nt++) {
      float p0 = ex2((s[nt][0] - mn0) * CEXP);
      float p1 = ex2((s[nt][1] - mn0) * CEXP);
      float p2 = ex2((s[nt][2] - mn1) * CEXP);
      float p3 = ex2((s[nt][3] - mn1) * CEXP);
      li0 += p0 + p1;
      li1 += p2 + p3;
      int kc = nt * 8 + kc0;
      sts32(Pb + r0 * (APITCH * 2) + kc * 2, packbf(p0, p1));
      sts32(Pb + (r0 + 8) * (APITCH * 2) + kc * 2, packbf(p2, p3));
    }
    mi0 = mn0; mi1 = mn1;
    __syncwarp();

    // ---- O += P V ----
    uint32_t Vb = s0 + AV_OFF(it & 1);
    #pragma unroll
    for (int kk = 0; kk < 4; kk++) {
      int kc = kk * 16 + kc0;
      uint32_t a[4];
      a[0] = lds32(Pb + r0 * (APITCH * 2) + kc * 2);
      a[1] = lds32(Pb + (r0 + 8) * (APITCH * 2) + kc * 2);
      a[2] = lds32(Pb + r0 * (APITCH * 2) + (kc + 8) * 2);
      a[3] = lds32(Pb + (r0 + 8) * (APITCH * 2) + (kc + 8) * 2);
      #pragma unroll
      for (int nt = 0; nt < 8; nt++) {
        int d = nt * 8 + r0;
        uint32_t b0 = lds32(Vb + d * (APITCH * 2) + kc * 2);
        uint32_t b1 = lds32(Vb + d * (APITCH * 2) + (kc + 8) * 2);
        mma_bf16(o[nt], a, b0, b1);
      }
    }
    __syncwarp();
  }

  // finalize
  li0 += __shfl_xor_sync(0xffffffffu, li0, 1);
  li0 += __shfl_xor_sync(0xffffffffu, li0, 2);
  li1 += __shfl_xor_sync(0xffffffffu, li1, 1);
  li1 += __shfl_xor_sync(0xffffffffu, li1, 2);
  float inv0 = 1.f / li0, inv1 = 1.f / li1;
  int gr0 = b * LJ + q0 + wid * 16 + r0;
  #pragma unroll
  for (int nt = 0; nt < 8; nt++) {
    int cn = h * HD + nt * 8 + kc0;
    *(uint32_t*)(Og + (size_t)gr0 * QN + cn) = packbf(o[nt][0] * inv0, o[nt][1] * inv0);
    *(uint32_t*)(Og + (size_t)(gr0 + 8) * QN + cn) = packbf(o[nt][2] * inv1, o[nt][3] * inv1);
  }
}

// ---------------------------------------------------------------------------
// Launch
// ---------------------------------------------------------------------------
extern "C" void kernel_launch(void* const* d_in, const int* in_sizes, int n_in,
                              void* d_out, int out_size) {
  const float* hv  = (const float*)d_in[0];
  const float* he  = (const float*)d_in[1];
  const float* lnv = (const float*)d_in[2];
  const float* wqv = (const float*)d_in[3];
  const float* wkv = (const float*)d_in[4];
  const float* wvv = (const float*)d_in[5];
  const float* wov = (const float*)d_in[6];
  const float* lne = (const float*)d_in[7];
  const float* wqe = (const float*)d_in[8];
  const float* wke = (const float*)d_in[9];
  const float* wve = (const float*)d_in[10];
  const float* woe = (const float*)d_in[11];
  const int* pv = (const int*)d_in[12];
  const int* pe = (const int*)d_in[13];
  float* out = (float*)d_out;

  bf16 *xhv, *xhe, *qh, *kh, *vt, *attn, *wh;
  cudaGetSymbolAddress((void**)&xhv, g_xh_v);
  cudaGetSymbolAddress((void**)&xhe, g_xh_e);
  cudaGetSymbolAddress((void**)&qh,  g_qh);
  cudaGetSymbolAddress((void**)&kh,  g_kh);
  cudaGetSymbolAddress((void**)&vt,  g_vt);
  cudaGetSymbolAddress((void**)&attn, g_attn);
  cudaGetSymbolAddress((void**)&wh,  g_wh);

  cudaFuncSetAttribute(gemm_bf16, cudaFuncAttributeMaxDynamicSharedMemorySize, GEMM_SMEM);
  cudaFuncSetAttribute(attn_mma, cudaFuncAttributeMaxDynamicSharedMemorySize, ATTN_SMEM);

  // transposed bf16 weight offsets in g_wh
  const int SQ = 960 * 960, SK = 960 * 320;
  bf16* cwqv = wh;
  bf16* cwkv = wh + SQ;
  bf16* cwvv = wh + SQ + SK;
  bf16* cwov = wh + SQ + 2 * SK;
  bf16* cwqe = wh + 2 * SQ + 2 * SK;
  bf16* cwke = wh + 3 * SQ + 2 * SK;
  bf16* cwve = wh + 3 * SQ + 3 * SK;
  bf16* cwoe = wh + 3 * SQ + 4 * SK;

  dim3 tb(32, 8);
  cvt_t<<<dim3(30, 30), tb>>>(wqv, cwqv, DMODEL, QN);
  cvt_t<<<dim3(10, 30), tb>>>(wkv, cwkv, DMODEL, KVN);
  cvt_t<<<dim3(10, 30), tb>>>(wvv, cwvv, DMODEL, KVN);
  cvt_t<<<dim3(30, 30), tb>>>(wov, cwov, QN, DMODEL);
  cvt_t<<<dim3(30, 30), tb>>>(wqe, cwqe, DMODEL, QN);
  cvt_t<<<dim3(10, 30), tb>>>(wke, cwke, DMODEL, KVN);
  cvt_t<<<dim3(10, 30), tb>>>(wve, cwve, DMODEL, KVN);
  cvt_t<<<dim3(30, 30), tb>>>(woe, cwoe, QN, DMODEL);

  // 1) RMSNorm (bf16 outputs)
  rmsnorm_kernel<<<NB * LV, 256>>>(hv, lnv, xhv);
  rmsnorm_kernel<<<NB * LE, 256>>>(he, lne, xhe);

  // 2) QKV projections
  gemm_bf16<<<dim3(QN / 64, 32), 256, GEMM_SMEM>>>(xhv, cwqv, nullptr, qh, nullptr, QN,  DMODEL, LV, 0,  0, 0);
  gemm_bf16<<<dim3(KVN / 64, 32), 256, GEMM_SMEM>>>(xhv, cwkv, nullptr, kh, nullptr, KVN, DMODEL, LV, 0,  0, 0);
  gemm_bf16<<<dim3(KVN / 64, 32), 256, GEMM_SMEM>>>(xhv, cwvv, nullptr, vt, nullptr, KVN, DMODEL, LV, 0,  0, 2);
  gemm_bf16<<<dim3(QN / 64, 1), 256, GEMM_SMEM>>>(xhe, cwqe, nullptr, qh, nullptr, QN,  DMODEL, LE, LV, 0, 0);
  gemm_bf16<<<dim3(KVN / 64, 1), 256, GEMM_SMEM>>>(xhe, cwke, nullptr, kh, nullptr, KVN, DMODEL, LE, LV, 0, 0);
  gemm_bf16<<<dim3(KVN / 64, 1), 256, GEMM_SMEM>>>(xhe, cwve, nullptr, vt, nullptr, KVN, DMODEL, LE, LV, 0, 2);

  // 3) RoPE on q and k (in place, bf16)
  int pq = NB * LJ * NH;
  int pk = NB * LJ * NKVH;
  rope_kernel<<<(pq + 7) / 8, 256>>>(qh, NH,   pq, pv, pe);
  rope_kernel<<<(pk + 7) / 8, 256>>>(kh, NKVH, pk, pv, pe);

  // 4) Attention
  attn_mma<<<dim3(LJ / 64, NH, NB), 128, ATTN_SMEM>>>(qh, kh, vt, attn);

  // 5) Output projection + residual
  gemm_bf16<<<dim3(QN / 64, 32), 256, GEMM_SMEM>>>(attn, cwov, out, nullptr, hv, QN, DMODEL, LV, 0,  1, 1);
  gemm_bf16<<<dim3(QN / 64, 1), 256, GEMM_SMEM>>>(attn, cwoe, out, nullptr, he, QN, DMODEL, LE, LV, 1, 1);
}

// round 6
// speedup vs baseline: 6.8116x; 1.1066x over previous
#include <cuda_runtime.h>
#include <cuda_bf16.h>
#include <math.h>
#include <stdint.h>

// Problem constants
#define NB 4
#define LV 2048
#define LE 64
#define LJ 2112        // LV + LE
#define DMODEL 960
#define NH 15
#define NKVH 5
#define HD 64
#define GQ 3           // NH / NKVH
#define QN (NH*HD)     // 960
#define KVN (NKVH*HD)  // 320
#define CEXP 0.18033688011112042f   // 0.125 * log2(e)

typedef __nv_bfloat16 bf16;

// Scratch (static device globals: allocation-free per harness rules)
__device__ bf16 g_xh_v[NB*LV*DMODEL];
__device__ bf16 g_xh_e[NB*LE*DMODEL];
__device__ bf16 g_qh[NB*LJ*QN];
__device__ bf16 g_kh[NB*LJ*KVN];
__device__ bf16 g_vt[NB*KVN*LJ];      // [b][kvh][d][l] transposed V
__device__ bf16 g_attn[NB*LJ*QN];
__device__ bf16 g_wh[4915200];        // bf16 transposed weights

// ---------------------------------------------------------------------------
// helpers
// ---------------------------------------------------------------------------
__device__ __forceinline__ uint32_t smem_u32(const void* p) {
  uint32_t a;
  asm("{ .reg .u64 t; cvta.to.shared.u64 t, %1; cvt.u32.u64 %0, t; }" : "=r"(a) : "l"(p));
  return a;
}
__device__ __forceinline__ float ex2(float x) {
  float y;
  asm("ex2.approx.ftz.f32 %0, %1;" : "=f"(y) : "f"(x));
  return y;
}
__device__ __forceinline__ uint32_t lds32(uint32_t a) {
  uint32_t v;
  asm volatile("ld.shared.b32 %0, [%1];" : "=r"(v) : "r"(a));
  return v;
}
__device__ __forceinline__ void cpa16(uint32_t dst, const void* src) {
  asm volatile("cp.async.cg.shared.global [%0], [%1], 16;" :: "r"(dst), "l"(src) : "memory");
}
#define CPA_COMMIT asm volatile("cp.async.commit_group;" ::: "memory")
#define CPA_WAIT0  asm volatile("cp.async.wait_group 0;" ::: "memory")

__device__ __forceinline__ uint32_t packbf(float x, float y) {
  __nv_bfloat162 h = __floats2bfloat162_rn(x, y);
  return *(uint32_t*)&h;
}

__device__ __forceinline__ void mma_bf16(float c[4], const uint32_t a[4],
                                         uint32_t b0, uint32_t b1) {
  asm volatile(
      "mma.sync.aligned.m16n8k16.row.col.f32.bf16.bf16.f32 "
      "{%0,%1,%2,%3}, {%4,%5,%6,%7}, {%8,%9}, {%0,%1,%2,%3};"
      : "+f"(c[0]), "+f"(c[1]), "+f"(c[2]), "+f"(c[3])
      : "r"(a[0]), "r"(a[1]), "r"(a[2]), "r"(a[3]), "r"(b0), "r"(b1));
}

// ---------------------------------------------------------------------------
// Weight transpose+convert: W fp32 [K][N] -> Wt bf16 [N][K]
// ---------------------------------------------------------------------------
__global__ void cvt_t(const float* __restrict__ W, bf16* __restrict__ Wt, int K, int N) {
  __shared__ float t[32][33];
  int n0 = blockIdx.x * 32, k0 = blockIdx.y * 32;
  int tx = threadIdx.x, ty = threadIdx.y;
  #pragma unroll
  for (int i = 0; i < 4; i++)
    t[ty + i * 8][tx] = W[(size_t)(k0 + ty + i * 8) * N + n0 + tx];
  __syncthreads();
  #pragma unroll
  for (int i = 0; i < 4; i++)
    Wt[(size_t)(n0 + ty + i * 8) * K + k0 + tx] = __float2bfloat16_rn(t[tx][ty + i * 8]);
}

// ---------------------------------------------------------------------------
// RMSNorm (bf16 output): one block per row, 256 threads over D=960
// ---------------------------------------------------------------------------
__global__ void rmsnorm_kernel(const float* __restrict__ x, const float* __restrict__ w,
                               bf16* __restrict__ out) {
  int row = blockIdx.x;
  const float* xr = x + (size_t)row * DMODEL;
  bf16* orow = out + (size_t)row * DMODEL;
  int t = threadIdx.x;
  float v[4];
  float ss = 0.f;
  #pragma unroll
  for (int i = 0; i < 4; i++) {
    int idx = t + i * 256;
    v[i] = (idx < DMODEL) ? xr[idx] : 0.f;
    ss += v[i] * v[i];
  }
  #pragma unroll
  for (int o = 16; o > 0; o >>= 1) ss += __shfl_xor_sync(0xffffffffu, ss, o);
  __shared__ float wsum[8];
  if ((t & 31) == 0) wsum[t >> 5] = ss;
  __syncthreads();
  if (t < 32) {
    float s = (t < 8) ? wsum[t] : 0.f;
    #pragma unroll
    for (int o = 4; o > 0; o >>= 1) s += __shfl_xor_sync(0xffffffffu, s, o);
    if (t == 0) wsum[0] = s;
  }
  __syncthreads();
  float rms = rsqrtf(wsum[0] * (1.f / DMODEL) + 1e-6f);
  #pragma unroll
  for (int i = 0; i < 4; i++) {
    int idx = t + i * 256;
    if (idx < DMODEL) orow[idx] = __float2bfloat16_rn(v[i] * rms * w[idx]);
  }
}

// ---------------------------------------------------------------------------
// bf16 mma GEMM. BM=256 BN=64 BK=64, 256 threads (8 warps 4x2, warp tile
// 64x32). cp.async double-buffered. Wt is [N][K] bf16 (pre-transposed).
// mode 0: bf16 out joint scatter; 1: fp32 out + resid; 2: transposed V out.
// ---------------------------------------------------------------------------
#define GBM 256
#define GPITCH 72
#define GABYTES (GBM*GPITCH*2)   // 36864
#define GBBYTES (64*GPITCH*2)    // 9216
#define GBUF (GABYTES+GBBYTES)   // 46080
#define GEMM_SMEM (2*GBUF)       // 92160

__global__ void __launch_bounds__(256)
gemm_bf16(const bf16* __restrict__ A, const bf16* __restrict__ Wt,
          float* __restrict__ Cf, bf16* __restrict__ Cb,
          const float* __restrict__ resid,
          int N, int K, int Lsrc, int l_off, int a_joint, int mode) {
  extern __shared__ char sm[];
  uint32_t s0 = smem_u32(sm);
  int tid = threadIdx.x;
  int wid = tid >> 5, lane = tid & 31;
  int wm = wid >> 1, wn = wid & 1;
  int m0 = blockIdx.y * GBM, n0 = blockIdx.x * 64;

  const bf16* asrc[8]; uint32_t adst[8];
  #pragma unroll
  for (int i = 0; i < 8; i++) {
    int idx = tid + 256 * i;
    int row = idx >> 3, ch = idx & 7;
    int m = m0 + row;
    int grow = a_joint ? ((m / Lsrc) * LJ + l_off + (m % Lsrc)) : m;
    asrc[i] = A + (size_t)grow * K + ch * 8;
    adst[i] = row * (GPITCH * 2) + ch * 16;
  }
  const bf16* bsrc[2]; uint32_t bdst[2];
  #pragma unroll
  for (int i = 0; i < 2; i++) {
    int idx = tid + 256 * i;
    int row = idx >> 3, ch = idx & 7;
    bsrc[i] = Wt + (size_t)(n0 + row) * K + ch * 8;
    bdst[i] = GABYTES + row * (GPITCH * 2) + ch * 16;
  }

  float c[4][4][4];
  #pragma unroll
  for (int mt = 0; mt < 4; mt++)
    #pragma unroll
    for (int nt = 0; nt < 4; nt++)
      #pragma unroll
      for (int i = 0; i < 4; i++) c[mt][nt][i] = 0.f;

  int nK = K >> 6;   // 15
  #pragma unroll
  for (int i = 0; i < 8; i++) cpa16(s0 + adst[i], asrc[i]);
  #pragma unroll
  for (int i = 0; i < 2; i++) cpa16(s0 + bdst[i], bsrc[i]);
  CPA_COMMIT;

  for (int it = 0; it < nK; it++) {
    CPA_WAIT0;
    __syncthreads();
    if (it + 1 < nK) {
      uint32_t boff = ((it + 1) & 1) * GBUF;
      int k0 = (it + 1) << 6;
      #pragma unroll
      for (int i = 0; i < 8; i++) cpa16(s0 + boff + adst[i], asrc[i] + k0);
      #pragma unroll
      for (int i = 0; i < 2; i++) cpa16(s0 + boff + bdst[i], bsrc[i] + k0);
      CPA_COMMIT;
    }
    uint32_t Ab = s0 + (it & 1) * GBUF;
    uint32_t Bb = Ab + GABYTES;
    int rb = wm * 64 + (lane >> 2);
    #pragma unroll
    for (int kk = 0; kk < 4; kk++) {
      int kc = kk * 16 + 2 * (lane & 3);
      uint32_t a[4][4];
      #pragma unroll
      for (int mt = 0; mt < 4; mt++) {
        int r = rb + mt * 16;
        a[mt][0] = lds32(Ab + r * (GPITCH * 2) + kc * 2);
        a[mt][1] = lds32(Ab + (r + 8) * (GPITCH * 2) + kc * 2);
        a[mt][2] = lds32(Ab + r * (GPITCH * 2) + (kc + 8) * 2);
        a[mt][3] = lds32(Ab + (r + 8) * (GPITCH * 2) + (kc + 8) * 2);
      }
      #pragma unroll
      for (int nt = 0; nt < 4; nt++) {
        int n = wn * 32 + nt * 8 + (lane >> 2);
        uint32_t b0 = lds32(Bb + n * (GPITCH * 2) + kc * 2);
        uint32_t b1 = lds32(Bb + n * (GPITCH * 2) + (kc + 8) * 2);
        #pragma unroll
        for (int mt = 0; mt < 4; mt++) mma_bf16(c[mt][nt], a[mt], b0, b1);
      }
    }
  }

  #pragma unroll
  for (int mt = 0; mt < 4; mt++) {
    #pragma unroll
    for (int hh = 0; hh < 2; hh++) {
      int m = m0 + wm * 64 + mt * 16 + (lane >> 2) + hh * 8;
      int bb = m / Lsrc, ll = m % Lsrc;
      int cr = bb * LJ + l_off + ll;
      #pragma unroll
      for (int nt = 0; nt < 4; nt++) {
        int cn = n0 + wn * 32 + nt * 8 + 2 * (lane & 3);
        float vx = c[mt][nt][2 * hh], vy = c[mt][nt][2 * hh + 1];
        if (mode == 0) {
          *(uint32_t*)(Cb + (size_t)cr * N + cn) = packbf(vx, vy);
        } else if (mode == 1) {
          float2 hv = *(const float2*)(resid + (size_t)m * N + cn);
          float2 o; o.x = vx + hv.x; o.y = vy + hv.y;
          *(float2*)(Cf + (size_t)cr * N + cn) = o;
        } else {
          int kvh = cn >> 6, d = cn & 63;
          size_t base = ((size_t)(bb * NKVH + kvh) * HD);
          Cb[(base + d) * LJ + l_off + ll] = __float2bfloat16_rn(vx);
          Cb[(base + d + 1) * LJ + l_off + ll] = __float2bfloat16_rn(vy);
        }
      }
    }
  }
}

// ---------------------------------------------------------------------------
// RoPE (in-place on bf16)
// ---------------------------------------------------------------------------
__global__ void rope_kernel(bf16* __restrict__ buf, int nh, int npairs,
                            const int* __restrict__ pv, const int* __restrict__ pe) {
  int pair = blockIdx.x * 8 + (threadIdx.x >> 5);
  if (pair >= npairs) return;
  int j = threadIdx.x & 31;
  int h = pair % nh;
  int r = pair / nh;
  int b = r / LJ;
  int l = r - b * LJ;
  int pos = (l < LV) ? pv[b * LV + l] : pe[b * LE + (l - LV)];
  double dinv = exp((double)j * (-9.210340371976184 / 32.0));  // 10000^(-j/32)
  float rad = (float)((double)pos * dinv);
  float sn, cs;
  sincosf(rad, &sn, &cs);
  bf16* p = buf + (size_t)r * (nh * HD) + h * HD;
  float x1 = __bfloat162float(p[j]);
  float x2 = __bfloat162float(p[j + 32]);
  p[j] = __float2bfloat16_rn(x1 * cs - x2 * sn);
  p[j + 32] = __float2bfloat16_rn(x2 * cs + x1 * sn);
}

// ---------------------------------------------------------------------------
// Flash attention, bf16 mma. Block = 128 threads (4 warps), 128 q rows for
// (head h, batch b): each warp owns 32 q rows (two m16 groups). 64-key KV
// tiles, cp.async double-buffered, V pre-transposed [d][l].
// P never touches smem: S accumulator layout == A-fragment layout when
// packed pairwise to bf16x2.
// ---------------------------------------------------------------------------
#define APITCH 72
#define ATBYTES (64*APITCH*2)     // 9216
#define AQBYTES (128*APITCH*2)    // 18432
#define AKOFF(bb) (AQBYTES + (bb)*ATBYTES)
#define AVOFF(bb) (AQBYTES + 2*ATBYTES + (bb)*ATBYTES)
#define ATTN_SMEM (AQBYTES + 4*ATBYTES)   // 55296

__global__ void __launch_bounds__(128)
attn_mma(const bf16* __restrict__ Qg, const bf16* __restrict__ Kg,
         const bf16* __restrict__ Vt, bf16* __restrict__ Og) {
  extern __shared__ char sm[];
  uint32_t s0 = smem_u32(sm);
  int tid = threadIdx.x;
  int wid = tid >> 5, lane = tid & 31;
  int h = blockIdx.y, b = blockIdx.z;
  int kvh = h / GQ;
  int q0 = blockIdx.x * 128;
  int nT = (q0 < LV) ? (LV / 64) : (LJ / 64);  // 32 or 33

  // cp.async chunk mappings
  int qrow[8], qch[8];
  #pragma unroll
  for (int i = 0; i < 8; i++) {
    int idx = tid + 128 * i;
    qrow[i] = idx >> 3;
    qch[i] = idx & 7;
  }
  int crow[4], cch[4];
  #pragma unroll
  for (int i = 0; i < 4; i++) {
    int idx = tid + 128 * i;
    crow[i] = idx >> 3;
    cch[i] = idx & 7;
  }
  const bf16* vbase = Vt + (size_t)(b * NKVH + kvh) * HD * LJ;

  // prologue: Q (clamped rows) + KV tile 0
  #pragma unroll
  for (int i = 0; i < 8; i++) {
    int gr = q0 + qrow[i];
    if (gr > LJ - 1) gr = LJ - 1;
    const bf16* src = Qg + ((size_t)(b * LJ + gr)) * QN + h * HD + qch[i] * 8;
    cpa16(s0 + qrow[i] * (APITCH * 2) + qch[i] * 16, src);
  }
  #pragma unroll
  for (int i = 0; i < 4; i++) {
    const bf16* ks = Kg + ((size_t)(b * LJ + crow[i])) * KVN + kvh * HD + cch[i] * 8;
    const bf16* vs = vbase + (size_t)crow[i] * LJ + cch[i] * 8;
    cpa16(s0 + AKOFF(0) + crow[i] * (APITCH * 2) + cch[i] * 16, ks);
    cpa16(s0 + AVOFF(0) + crow[i] * (APITCH * 2) + cch[i] * 16, vs);
  }
  CPA_COMMIT;

  float o[2][8][4];
  #pragma unroll
  for (int g = 0; g < 2; g++)
    #pragma unroll
    for (int nt = 0; nt < 8; nt++)
      #pragma unroll
      for (int i = 0; i < 4; i++) o[g][nt][i] = 0.f;
  float mi[2][2], li[2][2];
  #pragma unroll
  for (int g = 0; g < 2; g++) { mi[g][0] = mi[g][1] = -1e30f; li[g][0] = li[g][1] = 0.f; }

  uint32_t qf[2][4][4];
  int r0 = lane >> 2;
  int kc0 = 2 * (lane & 3);

  for (int it = 0; it < nT; it++) {
    CPA_WAIT0;
    __syncthreads();
    if (it + 1 < nT) {
      uint32_t kb = AKOFF((it + 1) & 1), vb = AVOFF((it + 1) & 1);
      int kr0 = (it + 1) * 64;
      #pragma unroll
      for (int i = 0; i < 4; i++) {
        const bf16* ks = Kg + ((size_t)(b * LJ + kr0 + crow[i])) * KVN + kvh * HD + cch[i] * 8;
        const bf16* vs = vbase + (size_t)crow[i] * LJ + kr0 + cch[i] * 8;
        cpa16(s0 + kb + crow[i] * (APITCH * 2) + cch[i] * 16, ks);
        cpa16(s0 + vb + crow[i] * (APITCH * 2) + cch[i] * 16, vs);
      }
      CPA_COMMIT;
    }
    if (it == 0) {
      #pragma unroll
      for (int g = 0; g < 2; g++) {
        int qr = wid * 32 + g * 16 + r0;
        #pragma unroll
        for (int kk = 0; kk < 4; kk++) {
          int kc = kk * 16 + kc0;
          qf[g][kk][0] = lds32(s0 + qr * (APITCH * 2) + kc * 2);
          qf[g][kk][1] = lds32(s0 + (qr + 8) * (APITCH * 2) + kc * 2);
          qf[g][kk][2] = lds32(s0 + qr * (APITCH * 2) + (kc + 8) * 2);
          qf[g][kk][3] = lds32(s0 + (qr + 8) * (APITCH * 2) + (kc + 8) * 2);
        }
      }
    }

    // ---- S = Q K^T (both row groups share K fragments) ----
    uint32_t Kb = s0 + AKOFF(it & 1);
    float s[2][8][4];
    #pragma unroll
    for (int nt = 0; nt < 8; nt++) {
      #pragma unroll
      for (int g = 0; g < 2; g++)
        s[g][nt][0] = s[g][nt][1] = s[g][nt][2] = s[g][nt][3] = 0.f;
      int key = nt * 8 + r0;
      #pragma unroll
      for (int kk = 0; kk < 4; kk++) {
        int kc = kk * 16 + kc0;
        uint32_t b0 = lds32(Kb + key * (APITCH * 2) + kc * 2);
        uint32_t b1 = lds32(Kb + key * (APITCH * 2) + (kc + 8) * 2);
        mma_bf16(s[0][nt], qf[0][kk], b0, b1);
        mma_bf16(s[1][nt], qf[1][kk], b0, b1);
      }
    }

    // causal mask (expert q-block, last KV tile only)
    if (q0 >= LV && it == nT - 1) {
      int tk = it * 64;
      #pragma unroll
      for (int g = 0; g < 2; g++) {
        int rl = q0 + wid * 32 + g * 16 + r0;
        #pragma unroll
        for (int nt = 0; nt < 8; nt++) {
          int key = tk + nt * 8 + kc0;
          if (key > rl)         s[g][nt][0] = -1e30f;
          if (key + 1 > rl)     s[g][nt][1] = -1e30f;
          if (key > rl + 8)     s[g][nt][2] = -1e30f;
          if (key + 1 > rl + 8) s[g][nt][3] = -1e30f;
        }
      }
    }

    // ---- online softmax (per row group); p overwrites s ----
    #pragma unroll
    for (int g = 0; g < 2; g++) {
      float tm0 = -1e30f, tm1 = -1e30f;
      #pragma unroll
      for (int nt = 0; nt < 8; nt++) {
        tm0 = fmaxf(tm0, fmaxf(s[g][nt][0], s[g][nt][1]));
        tm1 = fmaxf(tm1, fmaxf(s[g][nt][2], s[g][nt][3]));
      }
      tm0 = fmaxf(tm0, __shfl_xor_sync(0xffffffffu, tm0, 1));
      tm0 = fmaxf(tm0, __shfl_xor_sync(0xffffffffu, tm0, 2));
      tm1 = fmaxf(tm1, __shfl_xor_sync(0xffffffffu, tm1, 1));
      tm1 = fmaxf(tm1, __shfl_xor_sync(0xffffffffu, tm1, 2));
      float mn0 = fmaxf(mi[g][0], tm0), mn1 = fmaxf(mi[g][1], tm1);
      float cr0 = ex2((mi[g][0] - mn0) * CEXP), cr1 = ex2((mi[g][1] - mn1) * CEXP);
      li[g][0] *= cr0; li[g][1] *= cr1;
      #pragma unroll
      for (int nt = 0; nt < 8; nt++) {
        o[g][nt][0] *= cr0; o[g][nt][1] *= cr0;
        o[g][nt][2] *= cr1; o[g][nt][3] *= cr1;
      }
      #pragma unroll
      for (int nt = 0; nt < 8; nt++) {
        float p0 = ex2((s[g][nt][0] - mn0) * CEXP);
        float p1 = ex2((s[g][nt][1] - mn0) * CEXP);
        float p2 = ex2((s[g][nt][2] - mn1) * CEXP);
        float p3 = ex2((s[g][nt][3] - mn1) * CEXP);
        li[g][0] += p0 + p1;
        li[g][1] += p2 + p3;
        s[g][nt][0] = p0; s[g][nt][1] = p1; s[g][nt][2] = p2; s[g][nt][3] = p3;
      }
      mi[g][0] = mn0; mi[g][1] = mn1;
    }

    // ---- O += P V (P direct from registers; V fragments shared) ----
    uint32_t Vb = s0 + AVOFF(it & 1);
    #pragma unroll
    for (int kk = 0; kk < 4; kk++) {
      uint32_t a[2][4];
      #pragma unroll
      for (int g = 0; g < 2; g++) {
        a[g][0] = packbf(s[g][2 * kk][0], s[g][2 * kk][1]);
        a[g][1] = packbf(s[g][2 * kk][2], s[g][2 * kk][3]);
        a[g][2] = packbf(s[g][2 * kk + 1][0], s[g][2 * kk + 1][1]);
        a[g][3] = packbf(s[g][2 * kk + 1][2], s[g][2 * kk + 1][3]);
      }
      int kc = kk * 16 + kc0;
      #pragma unroll
      for (int nt = 0; nt < 8; nt++) {
        int d = nt * 8 + r0;
        uint32_t b0 = lds32(Vb + d * (APITCH * 2) + kc * 2);
        uint32_t b1 = lds32(Vb + d * (APITCH * 2) + (kc + 8) * 2);
        mma_bf16(o[0][nt], a[0], b0, b1);
        mma_bf16(o[1][nt], a[1], b0, b1);
      }
    }
  }

  // finalize
  #pragma unroll
  for (int g = 0; g < 2; g++) {
    if (q0 + wid * 32 + g * 16 >= LJ) continue;
    float l0 = li[g][0], l1 = li[g][1];
    l0 += __shfl_xor_sync(0xffffffffu, l0, 1);
    l0 += __shfl_xor_sync(0xffffffffu, l0, 2);
    l1 += __shfl_xor_sync(0xffffffffu, l1, 1);
    l1 += __shfl_xor_sync(0xffffffffu, l1, 2);
    float inv0 = 1.f / l0, inv1 = 1.f / l1;
    int gr0 = b * LJ + q0 + wid * 32 + g * 16 + r0;
    #pragma unroll
    for (int nt = 0; nt < 8; nt++) {
      int cn = h * HD + nt * 8 + kc0;
      *(uint32_t*)(Og + (size_t)gr0 * QN + cn) = packbf(o[g][nt][0] * inv0, o[g][nt][1] * inv0);
      *(uint32_t*)(Og + (size_t)(gr0 + 8) * QN + cn) = packbf(o[g][nt][2] * inv1, o[g][nt][3] * inv1);
    }
  }
}

// ---------------------------------------------------------------------------
// Launch
// ---------------------------------------------------------------------------
extern "C" void kernel_launch(void* const* d_in, const int* in_sizes, int n_in,
                              void* d_out, int out_size) {
  const float* hv  = (const float*)d_in[0];
  const float* he  = (const float*)d_in[1];
  const float* lnv = (const float*)d_in[2];
  const float* wqv = (const float*)d_in[3];
  const float* wkv = (const float*)d_in[4];
  const float* wvv = (const float*)d_in[5];
  const float* wov = (const float*)d_in[6];
  const float* lne = (const float*)d_in[7];
  const float* wqe = (const float*)d_in[8];
  const float* wke = (const float*)d_in[9];
  const float* wve = (const float*)d_in[10];
  const float* woe = (const float*)d_in[11];
  const int* pv = (const int*)d_in[12];
  const int* pe = (const int*)d_in[13];
  float* out = (float*)d_out;

  bf16 *xhv, *xhe, *qh, *kh, *vt, *attn, *wh;
  cudaGetSymbolAddress((void**)&xhv, g_xh_v);
  cudaGetSymbolAddress((void**)&xhe, g_xh_e);
  cudaGetSymbolAddress((void**)&qh,  g_qh);
  cudaGetSymbolAddress((void**)&kh,  g_kh);
  cudaGetSymbolAddress((void**)&vt,  g_vt);
  cudaGetSymbolAddress((void**)&attn, g_attn);
  cudaGetSymbolAddress((void**)&wh,  g_wh);

  cudaFuncSetAttribute(gemm_bf16, cudaFuncAttributeMaxDynamicSharedMemorySize, GEMM_SMEM);
  cudaFuncSetAttribute(attn_mma, cudaFuncAttributeMaxDynamicSharedMemorySize, ATTN_SMEM);

  const int SQ = 960 * 960, SK = 960 * 320;
  bf16* cwqv = wh;
  bf16* cwkv = wh + SQ;
  bf16* cwvv = wh + SQ + SK;
  bf16* cwov = wh + SQ + 2 * SK;
  bf16* cwqe = wh + 2 * SQ + 2 * SK;
  bf16* cwke = wh + 3 * SQ + 2 * SK;
  bf16* cwve = wh + 3 * SQ + 3 * SK;
  bf16* cwoe = wh + 3 * SQ + 4 * SK;

  dim3 tb(32, 8);
  cvt_t<<<dim3(30, 30), tb>>>(wqv, cwqv, DMODEL, QN);
  cvt_t<<<dim3(10, 30), tb>>>(wkv, cwkv, DMODEL, KVN);
  cvt_t<<<dim3(10, 30), tb>>>(wvv, cwvv, DMODEL, KVN);
  cvt_t<<<dim3(30, 30), tb>>>(wov, cwov, QN, DMODEL);
  cvt_t<<<dim3(30, 30), tb>>>(wqe, cwqe, DMODEL, QN);
  cvt_t<<<dim3(10, 30), tb>>>(wke, cwke, DMODEL, KVN);
  cvt_t<<<dim3(10, 30), tb>>>(wve, cwve, DMODEL, KVN);
  cvt_t<<<dim3(30, 30), tb>>>(woe, cwoe, QN, DMODEL);

  // 1) RMSNorm (bf16 outputs)
  rmsnorm_kernel<<<NB * LV, 256>>>(hv, lnv, xhv);
  rmsnorm_kernel<<<NB * LE, 256>>>(he, lne, xhe);

  // 2) QKV projections
  gemm_bf16<<<dim3(QN / 64, 32), 256, GEMM_SMEM>>>(xhv, cwqv, nullptr, qh, nullptr, QN,  DMODEL, LV, 0,  0, 0);
  gemm_bf16<<<dim3(KVN / 64, 32), 256, GEMM_SMEM>>>(xhv, cwkv, nullptr, kh, nullptr, KVN, DMODEL, LV, 0,  0, 0);
  gemm_bf16<<<dim3(KVN / 64, 32), 256, GEMM_SMEM>>>(xhv, cwvv, nullptr, vt, nullptr, KVN, DMODEL, LV, 0,  0, 2);
  gemm_bf16<<<dim3(QN / 64, 1), 256, GEMM_SMEM>>>(xhe, cwqe, nullptr, qh, nullptr, QN,  DMODEL, LE, LV, 0, 0);
  gemm_bf16<<<dim3(KVN / 64, 1), 256, GEMM_SMEM>>>(xhe, cwke, nullptr, kh, nullptr, KVN, DMODEL, LE, LV, 0, 0);
  gemm_bf16<<<dim3(KVN / 64, 1), 256, GEMM_SMEM>>>(xhe, cwve, nullptr, vt, nullptr, KVN, DMODEL, LE, LV, 0, 2);

  // 3) RoPE on q and k (in place, bf16)
  int pq = NB * LJ * NH;
  int pk = NB * LJ * NKVH;
  rope_kernel<<<(pq + 7) / 8, 256>>>(qh, NH,   pq, pv, pe);
  rope_kernel<<<(pk + 7) / 8, 256>>>(kh, NKVH, pk, pv, pe);

  // 4) Attention (128 q rows per block)
  attn_mma<<<dim3((LJ + 127) / 128, NH, NB), 128, ATTN_SMEM>>>(qh, kh, vt, attn);

  // 5) Output projection + residual
  gemm_bf16<<<dim3(QN / 64, 32), 256, GEMM_SMEM>>>(attn, cwov, out, nullptr, hv, QN, DMODEL, LV, 0,  1, 1);
  gemm_bf16<<<dim3(QN / 64, 1), 256, GEMM_SMEM>>>(attn, cwoe, out, nullptr, he, QN, DMODEL, LE, LV, 1, 1);
}